// round 1
// baseline (speedup 1.0000x reference)
#include <cuda_runtime.h>
#include <math.h>

#define BB 4
#define CC 64
#define CI 16
#define PP 4096
#define NCOL 64
#define TP 128

// ---------------- scratch (device globals; no allocations allowed) ----------
__device__ float g_q[BB*PP*CI];      // [b][p][o]
__device__ float g_k[BB*CI*PP];      // [b][o][p]
__device__ float g_v[BB*CC*PP];      // [b][c][p]
__device__ float g_out[BB*CC*PP];    // pre-gate output
__device__ float g_sum[BB*CC];
__device__ unsigned g_maxk[BB*CC];
__device__ float g_gate[BB*CC];

// monotone float<->uint key for atomicMax on floats (any sign)
__device__ __forceinline__ unsigned fkey(float f) {
    unsigned u = __float_as_uint(f);
    return (u & 0x80000000u) ? ~u : (u | 0x80000000u);
}
__device__ __forceinline__ float funkey(unsigned k) {
    unsigned u = (k & 0x80000000u) ? (k & 0x7FFFFFFFu) : ~k;
    return __uint_as_float(u);
}

// ---------------- K1: q/k/v projections -------------------------------------
// grid (PP/128, BB), 256 threads. thread = (p_local = tid&127, half = tid>>7)
__global__ void qkv_kernel(const float* __restrict__ ftr,
                           const float* __restrict__ wq, const float* __restrict__ bq,
                           const float* __restrict__ wk, const float* __restrict__ bk,
                           const float* __restrict__ wv, const float* __restrict__ bv)
{
    __shared__ float ws[96*64];   // rows: 0-15 wq, 16-31 wk, 32-95 wv
    __shared__ float bs[96];
    int tid = threadIdx.x;
    for (int i = tid; i < 16*64; i += 256) ws[i] = wq[i];
    for (int i = tid; i < 16*64; i += 256) ws[16*64 + i] = wk[i];
    for (int i = tid; i < 64*64; i += 256) ws[32*64 + i] = wv[i];
    if (tid < 16) bs[tid] = bq[tid];
    else if (tid < 32) bs[tid] = bk[tid - 16];
    else if (tid < 96) bs[tid] = bv[tid - 32];
    // zero SE reduction buffers once (this kernel finishes before attn starts)
    if (blockIdx.x == 0 && blockIdx.y == 0 && tid < BB*CC) {
        g_sum[tid] = 0.0f;
        g_maxk[tid] = 0u;
    }
    __syncthreads();

    int b = blockIdx.y;
    int p = blockIdx.x * 128 + (tid & 127);
    int half = tid >> 7;
    const float* x = ftr + (size_t)b*CC*PP + p;

    float acc[48];
#pragma unroll
    for (int i = 0; i < 48; i++) acc[i] = 0.0f;

    if (half == 0) {
        for (int c = 0; c < 64; c++) {
            float xc = x[(size_t)c*PP];
#pragma unroll
            for (int i = 0; i < 48; i++) acc[i] += ws[i*64 + c] * xc;
        }
        float* qp = g_q + ((size_t)b*PP + p)*CI;
#pragma unroll
        for (int o = 0; o < 16; o++) qp[o] = acc[o] + bs[o];
#pragma unroll
        for (int o = 0; o < 16; o++) g_k[((size_t)b*CI + o)*PP + p] = acc[16 + o] + bs[16 + o];
#pragma unroll
        for (int c2 = 0; c2 < 16; c2++) g_v[((size_t)b*CC + c2)*PP + p] = acc[32 + c2] + bs[32 + c2];
    } else {
        for (int c = 0; c < 64; c++) {
            float xc = x[(size_t)c*PP];
#pragma unroll
            for (int i = 0; i < 48; i++) acc[i] += ws[(48 + i)*64 + c] * xc;
        }
#pragma unroll
        for (int i = 0; i < 48; i++) g_v[((size_t)b*CC + 16 + i)*PP + p] = acc[i] + bs[48 + i];
    }
}

// ---------------- K2: streaming (flash-style) attention ----------------------
struct Smem2 {
    float q[TP][CI];        // 8 KB
    float v[CC][TP];        // 32 KB
    float s[TP][NCOL];      // 32 KB (scores, then exp weights)
    float red_m[4][NCOL];   // 1 KB
    float red_l[4][NCOL];   // 1 KB
};

extern __shared__ char smem_raw[];

// grid (PP/NCOL, BB), 256 threads. thread: j = tid&63 (column), g = tid>>6 (channel group of 16)
__global__ void attn_kernel(const float* __restrict__ ftr, const float* __restrict__ delta)
{
    Smem2& sm = *reinterpret_cast<Smem2*>(smem_raw);
    int tid = threadIdx.x;
    int j = tid & 63;
    int g = tid >> 6;
    int b = blockIdx.y;
    int col = blockIdx.x * NCOL + j;

    float kj[CI];
#pragma unroll
    for (int o = 0; o < CI; o++) kj[o] = g_k[((size_t)b*CI + o)*PP + col];

    float acc[16];
#pragma unroll
    for (int i = 0; i < 16; i++) acc[i] = 0.0f;
    float m = -INFINITY, l = 0.0f;

    const float* qbase = g_q + (size_t)b*PP*CI;
    const float* vbase = g_v + (size_t)b*CC*PP;

    for (int t = 0; t < PP/TP; t++) {
        int p0 = t * TP;
        // load q tile (2048 floats) — contiguous
        {
            const float4* qsrc = reinterpret_cast<const float4*>(qbase + (size_t)p0*CI);
            float4* qdst = reinterpret_cast<float4*>(&sm.q[0][0]);
            qdst[tid] = qsrc[tid];
            qdst[tid + 256] = qsrc[tid + 256];
        }
        // load v tile (64 rows x 128 floats)
#pragma unroll
        for (int r = 0; r < 8; r++) {
            int idx = r*256 + tid;      // float4 index, 0..2047
            int row = idx >> 5;
            int cp = idx & 31;
            reinterpret_cast<float4*>(&sm.v[row][0])[cp] =
                reinterpret_cast<const float4*>(vbase + (size_t)row*PP + p0)[cp];
        }
        __syncthreads();

        // scores for p in [g*32, g*32+32), column j
        float lmax = -INFINITY;
#pragma unroll 4
        for (int i = 0; i < 32; i++) {
            int p = g*32 + i;
            const float* qp = &sm.q[p][0];
            float s = 0.0f;
#pragma unroll
            for (int o = 0; o < 16; o++) s += qp[o] * kj[o];
            sm.s[p][j] = s;
            lmax = fmaxf(lmax, s);
        }
        sm.red_m[g][j] = lmax;
        __syncthreads();

        float mt = fmaxf(fmaxf(sm.red_m[0][j], sm.red_m[1][j]),
                         fmaxf(sm.red_m[2][j], sm.red_m[3][j]));
        float mnew = fmaxf(m, mt);
        float scale = __expf(m - mnew);     // first tile: exp(-inf)=0
#pragma unroll
        for (int i = 0; i < 16; i++) acc[i] *= scale;

        float lp = 0.0f;
#pragma unroll 4
        for (int i = 0; i < 32; i++) {
            int p = g*32 + i;
            float e = __expf(sm.s[p][j] - mnew);
            sm.s[p][j] = e;
            lp += e;
        }
        sm.red_l[g][j] = lp;
        __syncthreads();

        l = l*scale + (sm.red_l[0][j] + sm.red_l[1][j] + sm.red_l[2][j] + sm.red_l[3][j]);
        m = mnew;

        // G update: acc[cc] += sum_p v[c][p] * e[p][j]
        for (int p = 0; p < TP; p += 4) {
            float e0 = sm.s[p + 0][j];
            float e1 = sm.s[p + 1][j];
            float e2 = sm.s[p + 2][j];
            float e3 = sm.s[p + 3][j];
#pragma unroll
            for (int cc = 0; cc < 16; cc++) {
                const float4 v4 = *reinterpret_cast<const float4*>(&sm.v[g*16 + cc][p]);
                acc[cc] = fmaf(v4.x, e0, acc[cc]);
                acc[cc] = fmaf(v4.y, e1, acc[cc]);
                acc[cc] = fmaf(v4.z, e2, acc[cc]);
                acc[cc] = fmaf(v4.w, e3, acc[cc]);
            }
        }
        __syncthreads();
    }

    // epilogue: out = delta * G/l + ftr ; feed SE pooling reductions
    float inv_l = 1.0f / l;
    float dlt = delta[0];
    float outv[16];
    const float* fb = ftr + ((size_t)b*CC + g*16)*PP + col;
#pragma unroll
    for (int cc = 0; cc < 16; cc++) {
        float o = dlt * acc[cc] * inv_l + fb[(size_t)cc*PP];
        outv[cc] = o;
        g_out[((size_t)b*CC + g*16 + cc)*PP + col] = o;
    }
    unsigned lane = tid & 31;
#pragma unroll
    for (int cc = 0; cc < 16; cc++) {
        float s = outv[cc];
        float mx = outv[cc];
#pragma unroll
        for (int off = 16; off; off >>= 1) {
            s += __shfl_xor_sync(0xffffffffu, s, off);
            mx = fmaxf(mx, __shfl_xor_sync(0xffffffffu, mx, off));
        }
        if (lane == 0) {
            atomicAdd(&g_sum[b*CC + g*16 + cc], s);
            atomicMax(&g_maxk[b*CC + g*16 + cc], fkey(mx));
        }
    }
}

// ---------------- K3: SE gate -------------------------------------------------
__global__ void gate_kernel(const float* __restrict__ w_avg1, const float* __restrict__ w_avg2,
                            const float* __restrict__ w_max1, const float* __restrict__ w_max2)
{
    __shared__ float h_avg[BB][CI], h_max[BB][CI];
    __shared__ float favg[BB][CC], fmaxv[BB][CC];
    int tid = threadIdx.x;   // 256
    int b = tid >> 6, c = tid & 63;
    favg[b][c] = g_sum[tid] * (1.0f / (float)PP);
    fmaxv[b][c] = funkey(g_maxk[tid]);
    __syncthreads();
    if (tid < 128) {
        int bb = tid >> 5;
        int rest = tid & 31;
        int branch = rest >> 4;
        int o = rest & 15;
        const float* w1 = branch ? w_max1 : w_avg1;
        const float* f = branch ? &fmaxv[bb][0] : &favg[bb][0];
        float h = 0.0f;
        for (int cc2 = 0; cc2 < 64; cc2++) h += w1[o*64 + cc2] * f[cc2];
        h = fmaxf(h, 0.0f);
        if (branch) h_max[bb][o] = h; else h_avg[bb][o] = h;
    }
    __syncthreads();
    float a = 0.0f, mm = 0.0f;
#pragma unroll
    for (int o = 0; o < 16; o++) {
        a  += w_avg2[c*16 + o] * h_avg[b][o];
        mm += w_max2[c*16 + o] * h_max[b][o];
    }
    g_gate[tid] = 1.0f / (1.0f + __expf(-(a + mm)));
}

// ---------------- K4: apply gate ---------------------------------------------
__global__ void final_kernel(float* __restrict__ out)
{
    int idx = blockIdx.x * 256 + threadIdx.x;   // float4 index, total 262144
    float4 v = reinterpret_cast<const float4*>(g_out)[idx];
    float gval = g_gate[idx >> 10];   // (idx*4)/PP, PP=4096
    v.x *= gval; v.y *= gval; v.z *= gval; v.w *= gval;
    reinterpret_cast<float4*>(out)[idx] = v;
}

// ---------------- launch ------------------------------------------------------
extern "C" void kernel_launch(void* const* d_in, const int* in_sizes, int n_in,
                              void* d_out, int out_size)
{
    const float* ftr    = (const float*)d_in[0];
    const float* wq     = (const float*)d_in[1];
    const float* bq     = (const float*)d_in[2];
    const float* wk     = (const float*)d_in[3];
    const float* bk     = (const float*)d_in[4];
    const float* wv     = (const float*)d_in[5];
    const float* bv     = (const float*)d_in[6];
    const float* delta  = (const float*)d_in[7];
    const float* w_avg1 = (const float*)d_in[8];
    const float* w_avg2 = (const float*)d_in[9];
    const float* w_max1 = (const float*)d_in[10];
    const float* w_max2 = (const float*)d_in[11];
    float* out = (float*)d_out;

    cudaFuncSetAttribute(attn_kernel, cudaFuncAttributeMaxDynamicSharedMemorySize,
                         (int)sizeof(Smem2));

    qkv_kernel<<<dim3(PP/128, BB), 256>>>(ftr, wq, bq, wk, bk, wv, bv);
    attn_kernel<<<dim3(PP/NCOL, BB), 256, sizeof(Smem2)>>>(ftr, delta);
    gate_kernel<<<1, 256>>>(w_avg1, w_avg2, w_max1, w_max2);
    final_kernel<<<1024, 256>>>(out);
}